// round 6
// baseline (speedup 1.0000x reference)
#include <cuda_runtime.h>
#include <cuda_bf16.h>
#include <cstdint>

#define NMAX 50000
#define EMAX 800000
#define DIMH 128
#define NHEADS 8
#define HEADDIM 16
#define EXCAP 64   // per-warp smem capacity for ex values (deg max ~45 here)

// ---------------------------------------------------------------------------
// Scratch
// ---------------------------------------------------------------------------
__device__ float g_Q[(size_t)NMAX * DIMH];
__device__ float g_K[(size_t)NMAX * DIMH];
__device__ float g_V[(size_t)NMAX * DIMH];
__device__ float g_ex[(size_t)EMAX * NHEADS];   // overflow fallback only
__device__ int2  g_sedge[EMAX];                 // {src, eid}, CSR-ordered
__device__ int   g_count[NMAX];
__device__ int   g_off[NMAX + 1];
__device__ int   g_cur[NMAX];

// ---------------------------------------------------------------------------
// Helpers
// ---------------------------------------------------------------------------
__device__ __forceinline__ void red_add_u32(int* addr, unsigned v) {
    asm volatile("red.global.add.u32 [%0], %1;" :: "l"(addr), "r"(v) : "memory");
}
__device__ __forceinline__ uint32_t f32_to_tf32(float f) {
    uint32_t r;
    asm("cvt.rna.tf32.f32 %0, %1;" : "=r"(r) : "f"(f));
    return r;
}
__device__ __forceinline__ void mma_tf32(float (&c)[4],
                                         uint32_t a0, uint32_t a1,
                                         uint32_t a2, uint32_t a3,
                                         uint32_t b0, uint32_t b1) {
    asm volatile("mma.sync.aligned.m16n8k8.row.col.f32.tf32.tf32.f32 "
                 "{%0,%1,%2,%3}, {%4,%5,%6,%7}, {%8,%9}, {%0,%1,%2,%3};"
                 : "+f"(c[0]), "+f"(c[1]), "+f"(c[2]), "+f"(c[3])
                 : "r"(a0), "r"(a1), "r"(a2), "r"(a3), "r"(b0), "r"(b1));
}

// ---------------------------------------------------------------------------
// Counting sort by dst -> CSR
// ---------------------------------------------------------------------------
__global__ void k_zero_counts(int n) {
    int i = blockIdx.x * blockDim.x + threadIdx.x;
    if (i < n) g_count[i] = 0;
}

__global__ void k_hist(const int* __restrict__ ei, int E_) {
    int e = blockIdx.x * blockDim.x + threadIdx.x;
    if (e >= E_) return;
    red_add_u32(g_count + __ldg(ei + E_ + e), 1u);
}

__global__ __launch_bounds__(1024)
void k_scan(int n) {
    __shared__ int sums[1024];
    int t = threadIdx.x;
    int chunk = (n + 1023) >> 10;
    int lo = t * chunk;
    int hi = min(lo + chunk, n);

    int s = 0;
    for (int i = lo; i < hi; i++) s += g_count[i];
    sums[t] = s;
    __syncthreads();

    for (int off = 1; off < 1024; off <<= 1) {
        int v = 0;
        if (t >= off) v = sums[t - off];
        __syncthreads();
        if (t >= off) sums[t] += v;
        __syncthreads();
    }

    int run = (t > 0) ? sums[t - 1] : 0;
    for (int i = lo; i < hi; i++) {
        int c = g_count[i];
        g_off[i] = run;
        g_cur[i] = run;
        run += c;
    }
    if (t == 1023) g_off[n] = run;
}

__global__ void k_scatter(const int* __restrict__ ei, int E_) {
    int e = blockIdx.x * blockDim.x + threadIdx.x;
    if (e >= E_) return;
    int src = __ldg(ei + e);
    int dst = __ldg(ei + E_ + e);
    int pos = atomicAdd(g_cur + dst, 1);
    g_sedge[pos] = make_int2(src, e);
}

// ---------------------------------------------------------------------------
// GEMM: tf32 mma.sync.  out = x @ W^T + b.
// ---------------------------------------------------------------------------
#define BK 32
#define SPAD 36

__global__ __launch_bounds__(256)
void gemm_qkv_mma(const float* __restrict__ x,
                  const float* __restrict__ WQ, const float* __restrict__ bQ,
                  const float* __restrict__ WK, const float* __restrict__ bK,
                  const float* __restrict__ WV, const float* __restrict__ bV,
                  int n) {
    const float* W;
    const float* bias;
    float* out;
    if (blockIdx.y == 0)      { W = WQ; bias = bQ; out = g_Q; }
    else if (blockIdx.y == 1) { W = WK; bias = bK; out = g_K; }
    else                      { W = WV; bias = bV; out = g_V; }

    __shared__ uint32_t As[128][SPAD];
    __shared__ uint32_t Bs[128][SPAD];

    const int tid  = threadIdx.x;
    const int wid  = tid >> 5;
    const int lane = tid & 31;
    const int g    = lane >> 2;
    const int t    = lane & 3;
    const int row0 = blockIdx.x * 128;
    const int mrow = wid * 16;

    float acc[16][4];
#pragma unroll
    for (int nt = 0; nt < 16; nt++)
#pragma unroll
        for (int j = 0; j < 4; j++) acc[nt][j] = 0.0f;

    for (int kc = 0; kc < DIMH; kc += BK) {
#pragma unroll
        for (int i = 0; i < 4; i++) {
            int idx = tid + i * 256;
            int row = idx >> 3;
            int c4  = idx & 7;
            int gr  = row0 + row;
            float4 a = make_float4(0.f, 0.f, 0.f, 0.f);
            if (gr < n) a = *(const float4*)(x + (size_t)gr * DIMH + kc + c4 * 4);
            As[row][c4 * 4 + 0] = f32_to_tf32(a.x);
            As[row][c4 * 4 + 1] = f32_to_tf32(a.y);
            As[row][c4 * 4 + 2] = f32_to_tf32(a.z);
            As[row][c4 * 4 + 3] = f32_to_tf32(a.w);

            float4 w = *(const float4*)(W + (size_t)row * DIMH + kc + c4 * 4);
            Bs[row][c4 * 4 + 0] = f32_to_tf32(w.x);
            Bs[row][c4 * 4 + 1] = f32_to_tf32(w.y);
            Bs[row][c4 * 4 + 2] = f32_to_tf32(w.z);
            Bs[row][c4 * 4 + 3] = f32_to_tf32(w.w);
        }
        __syncthreads();

#pragma unroll
        for (int ks = 0; ks < BK / 8; ks++) {
            int k0 = ks * 8;
            uint32_t a0 = As[mrow + g][k0 + t];
            uint32_t a1 = As[mrow + g + 8][k0 + t];
            uint32_t a2 = As[mrow + g][k0 + t + 4];
            uint32_t a3 = As[mrow + g + 8][k0 + t + 4];
#pragma unroll
            for (int nt = 0; nt < 16; nt++) {
                uint32_t b0 = Bs[nt * 8 + g][k0 + t];
                uint32_t b1 = Bs[nt * 8 + g][k0 + t + 4];
                mma_tf32(acc[nt], a0, a1, a2, a3, b0, b1);
            }
        }
        __syncthreads();
    }

    int r0 = row0 + mrow + g;
    int r1 = r0 + 8;
#pragma unroll
    for (int nt = 0; nt < 16; nt++) {
        int c = nt * 8 + 2 * t;
        float bx = __ldg(bias + c), by = __ldg(bias + c + 1);
        if (r0 < n) {
            float2 v0 = make_float2(acc[nt][0] + bx, acc[nt][1] + by);
            *(float2*)(out + (size_t)r0 * DIMH + c) = v0;
        }
        if (r1 < n) {
            float2 v1 = make_float2(acc[nt][2] + bx, acc[nt][3] + by);
            *(float2*)(out + (size_t)r1 * DIMH + c) = v1;
        }
    }
}

// ---------------------------------------------------------------------------
// CSR attention: ONE WARP PER DESTINATION, high-MLP version.
//  - edge records (src,eid) prefetched 32-at-a-time with one coalesced load
//  - K/V rows + biases loaded 4 edges ahead (independent LDGs, MLP>=8)
//  - ex kept in per-warp smem (cap 64; global fallback beyond)
// ---------------------------------------------------------------------------
__global__ __launch_bounds__(256)
void csr_edge(const float* __restrict__ ebias,
              int n,
              float* __restrict__ out_h,
              float* __restrict__ out_alpha) {
    __shared__ float sEx[8][EXCAP][NHEADS];

    int d    = (blockIdx.x * blockDim.x + threadIdx.x) >> 5;
    int wid  = (threadIdx.x >> 5);
    int lane = threadIdx.x & 31;
    if (d >= n) return;

    const int beg = g_off[d];
    const int end = g_off[d + 1];
    const int h   = lane >> 2;

    float4 q = *(const float4*)(g_Q + (size_t)d * DIMH + lane * 4);
    float ssum = 0.0f;

    // ---- Pass 1: scores -> ex -> denominator ----
    for (int cb = beg; cb < end; cb += 32) {
        int m = min(32, end - cb);
        int2 se = make_int2(0, 0);
        if (lane < m) se = g_sedge[cb + lane];

        for (int i = 0; i < m; i += 4) {
            int cnt = min(4, m - i);
            float4 k[4];
            float  bs[4];
#pragma unroll
            for (int j = 0; j < 4; j++) {
                if (j < cnt) {
                    int s   = __shfl_sync(0xffffffffu, se.x, i + j);
                    int eid = __shfl_sync(0xffffffffu, se.y, i + j);
                    k[j]  = *(const float4*)(g_K + (size_t)s * DIMH + lane * 4);
                    bs[j] = __ldg(ebias + (size_t)eid * NHEADS + h);
                }
            }
#pragma unroll
            for (int j = 0; j < 4; j++) {
                if (j < cnt) {
                    float dp = q.x * k[j].x + q.y * k[j].y
                             + q.z * k[j].z + q.w * k[j].w;
                    dp += __shfl_xor_sync(0xffffffffu, dp, 1);
                    dp += __shfl_xor_sync(0xffffffffu, dp, 2);
                    float ex = __expf(dp * 0.25f + bs[j]);
                    ssum += ex;
                    int pl = cb - beg + i + j;
                    if ((lane & 3) == 0) {
                        if (pl < EXCAP) sEx[wid][pl][h] = ex;
                        else g_ex[(size_t)(cb + i + j) * NHEADS + h] = ex;
                    }
                }
            }
        }
    }

    float inv  = 1.0f / ssum;                                     // per head
    float invh = __shfl_sync(0xffffffffu, inv, (lane & 7) * 4);   // for lane<8

    // ---- Pass 2: alpha, aggregate V, write alpha ----
    float4 acc = make_float4(0.f, 0.f, 0.f, 0.f);
    for (int cb = beg; cb < end; cb += 32) {
        int m = min(32, end - cb);
        int2 se = make_int2(0, 0);
        if (lane < m) se = g_sedge[cb + lane];

        for (int i = 0; i < m; i += 4) {
            int cnt = min(4, m - i);
            float4 v[4];
            float  exj[4];
            float  exl[4];
#pragma unroll
            for (int j = 0; j < 4; j++) {
                if (j < cnt) {
                    int s  = __shfl_sync(0xffffffffu, se.x, i + j);
                    int pl = cb - beg + i + j;
                    v[j] = *(const float4*)(g_V + (size_t)s * DIMH + lane * 4);
                    if (pl < EXCAP) {
                        exj[j] = sEx[wid][pl][h];
                        exl[j] = (lane < NHEADS) ? sEx[wid][pl][lane] : 0.f;
                    } else {
                        exj[j] = g_ex[(size_t)(cb + i + j) * NHEADS + h];
                        exl[j] = (lane < NHEADS)
                               ? g_ex[(size_t)(cb + i + j) * NHEADS + lane] : 0.f;
                    }
                }
            }
#pragma unroll
            for (int j = 0; j < 4; j++) {
                if (j < cnt) {
                    float alpha = exj[j] * inv;
                    acc.x += alpha * v[j].x;
                    acc.y += alpha * v[j].y;
                    acc.z += alpha * v[j].z;
                    acc.w += alpha * v[j].w;
                    int eid = __shfl_sync(0xffffffffu, se.y, i + j);
                    if (lane < NHEADS)
                        out_alpha[(size_t)eid * NHEADS + lane] = exl[j] * invh;
                }
            }
        }
    }

    *(float4*)(out_h + (size_t)d * DIMH + lane * 4) = acc;
}

// ---------------------------------------------------------------------------
// Launch
// ---------------------------------------------------------------------------
extern "C" void kernel_launch(void* const* d_in, const int* in_sizes, int n_in,
                              void* d_out, int out_size) {
    const float* x     = (const float*)d_in[0];
    const int*   ei    = (const int*)d_in[1];
    const float* ebias = (const float*)d_in[2];
    const float* WQ    = (const float*)d_in[3];
    const float* bQ    = (const float*)d_in[4];
    const float* WK    = (const float*)d_in[5];
    const float* bK    = (const float*)d_in[6];
    const float* WV    = (const float*)d_in[7];
    const float* bV    = (const float*)d_in[8];

    int n = in_sizes[0] / DIMH;     // 50000
    int e = in_sizes[1] / 2;        // 800000

    float* out_h = (float*)d_out;
    float* out_alpha = out_h + (size_t)n * DIMH;

    // --- counting sort by dst -> CSR ---
    k_zero_counts<<<(n + 255) / 256, 256>>>(n);
    k_hist<<<(e + 255) / 256, 256>>>(ei, e);
    k_scan<<<1, 1024>>>(n);
    k_scatter<<<(e + 255) / 256, 256>>>(ei, e);

    // --- QKV projections (tf32 mma.sync) ---
    {
        dim3 grid((n + 127) / 128, 3);
        gemm_qkv_mma<<<grid, 256>>>(x, WQ, bQ, WK, bK, WV, bV, n);
    }

    // --- CSR attention: warp per destination node ---
    {
        long long threads = (long long)n * 32;
        int blocks = (int)((threads + 255) / 256);
        csr_edge<<<blocks, 256>>>(ebias, n, out_h, out_alpha);
    }
}

// round 7
// speedup vs baseline: 1.7124x; 1.7124x over previous
#include <cuda_runtime.h>
#include <cuda_bf16.h>
#include <cuda_fp16.h>
#include <cstdint>

#define NMAX 50000
#define EMAX 800000
#define DIMH 128
#define NHEADS 8
#define HEADDIM 16

// ---------------------------------------------------------------------------
// Scratch (fp16 QKV to halve gather traffic; fp32 elsewhere)
// ---------------------------------------------------------------------------
__device__ __half g_Q[(size_t)NMAX * DIMH];
__device__ __half g_K[(size_t)NMAX * DIMH];
__device__ __half g_V[(size_t)NMAX * DIMH];
__device__ float  g_ex[(size_t)EMAX * NHEADS];
__device__ float  g_segsum[(size_t)NMAX * NHEADS];

// ---------------------------------------------------------------------------
// Helpers
// ---------------------------------------------------------------------------
__device__ __forceinline__ void red_add_v4(float* addr, float4 v) {
    asm volatile("red.global.add.v4.f32 [%0], {%1, %2, %3, %4};"
                 :: "l"(addr), "f"(v.x), "f"(v.y), "f"(v.z), "f"(v.w) : "memory");
}
__device__ __forceinline__ void red_add_f32(float* addr, float v) {
    asm volatile("red.global.add.f32 [%0], %1;" :: "l"(addr), "f"(v) : "memory");
}
__device__ __forceinline__ uint32_t f32_to_tf32(float f) {
    uint32_t r;
    asm("cvt.rna.tf32.f32 %0, %1;" : "=r"(r) : "f"(f));
    return r;
}
__device__ __forceinline__ void mma_tf32(float (&c)[4],
                                         uint32_t a0, uint32_t a1,
                                         uint32_t a2, uint32_t a3,
                                         uint32_t b0, uint32_t b1) {
    asm volatile("mma.sync.aligned.m16n8k8.row.col.f32.tf32.tf32.f32 "
                 "{%0,%1,%2,%3}, {%4,%5,%6,%7}, {%8,%9}, {%0,%1,%2,%3};"
                 : "+f"(c[0]), "+f"(c[1]), "+f"(c[2]), "+f"(c[3])
                 : "r"(a0), "r"(a1), "r"(a2), "r"(a3), "r"(b0), "r"(b1));
}

// ---------------------------------------------------------------------------
// Kernel 0: zero h output + segment sums
// ---------------------------------------------------------------------------
__global__ void init_zero(float* __restrict__ out_h, int n) {
    int i = blockIdx.x * blockDim.x + threadIdx.x;
    if (i < n * DIMH) out_h[i] = 0.0f;
    if (i < n * NHEADS) g_segsum[i] = 0.0f;
}

// ---------------------------------------------------------------------------
// Kernel 1: tf32 mma.sync GEMM.  out(fp16) = x @ W^T + b.  grid.y -> {Q,K,V}
// ---------------------------------------------------------------------------
#define BK 32
#define SPAD 36

__global__ __launch_bounds__(256)
void gemm_qkv_mma(const float* __restrict__ x,
                  const float* __restrict__ WQ, const float* __restrict__ bQ,
                  const float* __restrict__ WK, const float* __restrict__ bK,
                  const float* __restrict__ WV, const float* __restrict__ bV,
                  int n) {
    const float* W;
    const float* bias;
    __half* out;
    if (blockIdx.y == 0)      { W = WQ; bias = bQ; out = g_Q; }
    else if (blockIdx.y == 1) { W = WK; bias = bK; out = g_K; }
    else                      { W = WV; bias = bV; out = g_V; }

    __shared__ uint32_t As[128][SPAD];
    __shared__ uint32_t Bs[128][SPAD];

    const int tid  = threadIdx.x;
    const int wid  = tid >> 5;
    const int lane = tid & 31;
    const int g    = lane >> 2;
    const int t    = lane & 3;
    const int row0 = blockIdx.x * 128;
    const int mrow = wid * 16;

    float acc[16][4];
#pragma unroll
    for (int nt = 0; nt < 16; nt++)
#pragma unroll
        for (int j = 0; j < 4; j++) acc[nt][j] = 0.0f;

    for (int kc = 0; kc < DIMH; kc += BK) {
#pragma unroll
        for (int i = 0; i < 4; i++) {
            int idx = tid + i * 256;
            int row = idx >> 3;
            int c4  = idx & 7;
            int gr  = row0 + row;
            float4 a = make_float4(0.f, 0.f, 0.f, 0.f);
            if (gr < n) a = *(const float4*)(x + (size_t)gr * DIMH + kc + c4 * 4);
            As[row][c4 * 4 + 0] = f32_to_tf32(a.x);
            As[row][c4 * 4 + 1] = f32_to_tf32(a.y);
            As[row][c4 * 4 + 2] = f32_to_tf32(a.z);
            As[row][c4 * 4 + 3] = f32_to_tf32(a.w);

            float4 w = *(const float4*)(W + (size_t)row * DIMH + kc + c4 * 4);
            Bs[row][c4 * 4 + 0] = f32_to_tf32(w.x);
            Bs[row][c4 * 4 + 1] = f32_to_tf32(w.y);
            Bs[row][c4 * 4 + 2] = f32_to_tf32(w.z);
            Bs[row][c4 * 4 + 3] = f32_to_tf32(w.w);
        }
        __syncthreads();

#pragma unroll
        for (int ks = 0; ks < BK / 8; ks++) {
            int k0 = ks * 8;
            uint32_t a0 = As[mrow + g][k0 + t];
            uint32_t a1 = As[mrow + g + 8][k0 + t];
            uint32_t a2 = As[mrow + g][k0 + t + 4];
            uint32_t a3 = As[mrow + g + 8][k0 + t + 4];
#pragma unroll
            for (int nt = 0; nt < 16; nt++) {
                uint32_t b0 = Bs[nt * 8 + g][k0 + t];
                uint32_t b1 = Bs[nt * 8 + g][k0 + t + 4];
                mma_tf32(acc[nt], a0, a1, a2, a3, b0, b1);
            }
        }
        __syncthreads();
    }

    // Epilogue: add bias, convert to fp16, store half2
    int r0 = row0 + mrow + g;
    int r1 = r0 + 8;
#pragma unroll
    for (int nt = 0; nt < 16; nt++) {
        int c = nt * 8 + 2 * t;
        float bx = __ldg(bias + c), by = __ldg(bias + c + 1);
        if (r0 < n) {
            __half2 v0 = __floats2half2_rn(acc[nt][0] + bx, acc[nt][1] + by);
            *(__half2*)(out + (size_t)r0 * DIMH + c) = v0;
        }
        if (r1 < n) {
            __half2 v1 = __floats2half2_rn(acc[nt][2] + bx, acc[nt][3] + by);
            *(__half2*)(out + (size_t)r1 * DIMH + c) = v1;
        }
    }
}

// ---------------------------------------------------------------------------
// Kernel 2 (FUSED): warp per edge.  fp16 Q/K/V loads (8B per lane),
// fp32 math, REDG fp32 outputs.  Same structure as the 250us R4 kernel.
// ---------------------------------------------------------------------------
__global__ __launch_bounds__(256)
void fused_edge(const int* __restrict__ ei,
                const float* __restrict__ ebias,
                int E_, float* __restrict__ out_h) {
    int e    = (blockIdx.x * blockDim.x + threadIdx.x) >> 5;
    int lane = threadIdx.x & 31;
    if (e >= E_) return;

    int src = __ldg(ei + e);
    int dst = __ldg(ei + E_ + e);

    // lane covers elements [4*lane, 4*lane+4) of the 128-wide row
    __half2 q2[2], k2[2];
    *(uint2*)q2 = *(const uint2*)(g_Q + (size_t)dst * DIMH + lane * 4);
    *(uint2*)k2 = *(const uint2*)(g_K + (size_t)src * DIMH + lane * 4);

    float2 qa = __half22float2(q2[0]), qb = __half22float2(q2[1]);
    float2 ka = __half22float2(k2[0]), kb = __half22float2(k2[1]);

    float p = qa.x * ka.x + qa.y * ka.y + qb.x * kb.x + qb.y * kb.y;
    p += __shfl_xor_sync(0xffffffffu, p, 1);
    p += __shfl_xor_sync(0xffffffffu, p, 2);

    int h = lane >> 2;
    float bias = __ldg(ebias + (size_t)e * NHEADS + h);
    float ex = __expf(p * 0.25f + bias);

    if ((lane & 3) == 0) {
        g_ex[(size_t)e * NHEADS + h] = ex;
        red_add_f32(g_segsum + (size_t)dst * NHEADS + h, ex);
    }

    __half2 v2[2];
    *(uint2*)v2 = *(const uint2*)(g_V + (size_t)src * DIMH + lane * 4);
    float2 va = __half22float2(v2[0]), vb = __half22float2(v2[1]);

    float4 v = make_float4(va.x * ex, va.y * ex, vb.x * ex, vb.y * ex);
    red_add_v4(out_h + (size_t)dst * DIMH + lane * 4, v);
}

// ---------------------------------------------------------------------------
// Kernel 3: normalize node outputs
// ---------------------------------------------------------------------------
__global__ void normalize_nodes(float* __restrict__ out_h, int n) {
    int t = blockIdx.x * blockDim.x + threadIdx.x;
    if (t >= n * 32) return;
    int i = t >> 5;
    int c4 = t & 31;
    float s = g_segsum[(size_t)i * NHEADS + (c4 >> 2)];
    float inv = 1.0f / s;
    float4 v = *(float4*)(out_h + (size_t)i * DIMH + c4 * 4);
    v.x *= inv; v.y *= inv; v.z *= inv; v.w *= inv;
    *(float4*)(out_h + (size_t)i * DIMH + c4 * 4) = v;
}

// ---------------------------------------------------------------------------
// Kernel 4: alpha = ex / segsum[dst]
// ---------------------------------------------------------------------------
__global__ void write_alpha(const int* __restrict__ ei, int E_,
                            float* __restrict__ out_alpha) {
    int e = blockIdx.x * blockDim.x + threadIdx.x;
    if (e >= E_) return;
    int dst = __ldg(ei + E_ + e);

    float4 e0 = *(const float4*)(g_ex + (size_t)e * NHEADS);
    float4 e1 = *(const float4*)(g_ex + (size_t)e * NHEADS + 4);
    float4 s0 = *(const float4*)(g_segsum + (size_t)dst * NHEADS);
    float4 s1 = *(const float4*)(g_segsum + (size_t)dst * NHEADS + 4);

    e0.x /= s0.x; e0.y /= s0.y; e0.z /= s0.z; e0.w /= s0.w;
    e1.x /= s1.x; e1.y /= s1.y; e1.z /= s1.z; e1.w /= s1.w;

    *(float4*)(out_alpha + (size_t)e * NHEADS)     = e0;
    *(float4*)(out_alpha + (size_t)e * NHEADS + 4) = e1;
}

// ---------------------------------------------------------------------------
// Launch
// ---------------------------------------------------------------------------
extern "C" void kernel_launch(void* const* d_in, const int* in_sizes, int n_in,
                              void* d_out, int out_size) {
    const float* x     = (const float*)d_in[0];
    const int*   ei    = (const int*)d_in[1];
    const float* ebias = (const float*)d_in[2];
    const float* WQ    = (const float*)d_in[3];
    const float* bQ    = (const float*)d_in[4];
    const float* WK    = (const float*)d_in[5];
    const float* bK    = (const float*)d_in[6];
    const float* WV    = (const float*)d_in[7];
    const float* bV    = (const float*)d_in[8];

    int n = in_sizes[0] / DIMH;     // 50000
    int e = in_sizes[1] / 2;        // 800000

    float* out_h = (float*)d_out;
    float* out_alpha = out_h + (size_t)n * DIMH;

    // 0) init
    {
        int blocks = (n * DIMH + 255) / 256;
        init_zero<<<blocks, 256>>>(out_h, n);
    }
    // 1) QKV projections (tf32 mma.sync, fp16 output)
    {
        dim3 grid((n + 127) / 128, 3);
        gemm_qkv_mma<<<grid, 256>>>(x, WQ, bQ, WK, bK, WV, bV, n);
    }
    // 2) fused edge pass
    {
        long long threads = (long long)e * 32;
        int blocks = (int)((threads + 255) / 256);
        fused_edge<<<blocks, 256>>>(ei, ebias, e, out_h);
    }
    // 3) normalize
    {
        int blocks = (n * 32 + 255) / 256;
        normalize_nodes<<<blocks, 256>>>(out_h, n);
    }
    // 4) alpha
    {
        int blocks = (e + 255) / 256;
        write_alpha<<<blocks, 256>>>(ei, e, out_alpha);
    }
}

// round 8
// speedup vs baseline: 1.8342x; 1.0712x over previous
#include <cuda_runtime.h>
#include <cuda_bf16.h>
#include <cuda_fp16.h>
#include <cstdint>

#define NMAX 50000
#define EMAX 800000
#define DIMH 128
#define NHEADS 8
#define HEADDIM 16

// ---------------------------------------------------------------------------
// Scratch (fp16 QKV to halve gather traffic; fp32 elsewhere)
// ---------------------------------------------------------------------------
__device__ __half g_Q[(size_t)NMAX * DIMH];
__device__ __half g_K[(size_t)NMAX * DIMH];
__device__ __half g_V[(size_t)NMAX * DIMH];
__device__ float  g_ex[(size_t)EMAX * NHEADS];
__device__ float  g_segsum[(size_t)NMAX * NHEADS];

// ---------------------------------------------------------------------------
// Helpers
// ---------------------------------------------------------------------------
__device__ __forceinline__ void red_add_v4(float* addr, float4 v) {
    asm volatile("red.global.add.v4.f32 [%0], {%1, %2, %3, %4};"
                 :: "l"(addr), "f"(v.x), "f"(v.y), "f"(v.z), "f"(v.w) : "memory");
}
__device__ __forceinline__ void red_add_f32(float* addr, float v) {
    asm volatile("red.global.add.f32 [%0], %1;" :: "l"(addr), "f"(v) : "memory");
}
__device__ __forceinline__ uint32_t f32_to_tf32(float f) {
    uint32_t r;
    asm("cvt.rna.tf32.f32 %0, %1;" : "=r"(r) : "f"(f));
    return r;
}
__device__ __forceinline__ void mma_tf32(float (&c)[4],
                                         uint32_t a0, uint32_t a1,
                                         uint32_t a2, uint32_t a3,
                                         uint32_t b0, uint32_t b1) {
    asm volatile("mma.sync.aligned.m16n8k8.row.col.f32.tf32.tf32.f32 "
                 "{%0,%1,%2,%3}, {%4,%5,%6,%7}, {%8,%9}, {%0,%1,%2,%3};"
                 : "+f"(c[0]), "+f"(c[1]), "+f"(c[2]), "+f"(c[3])
                 : "r"(a0), "r"(a1), "r"(a2), "r"(a3), "r"(b0), "r"(b1));
}

// ---------------------------------------------------------------------------
// Kernel 1: tf32 mma.sync GEMM.  out(fp16) = x @ W^T + b.  grid.y -> {Q,K,V}
// Q-branch CTAs additionally zero their slice of out_h and g_segsum
// (disjoint regions; hides under GEMM compute; removes the init kernel).
// ---------------------------------------------------------------------------
#define BK 32
#define SPAD 36

__global__ __launch_bounds__(256)
void gemm_qkv_mma(const float* __restrict__ x,
                  const float* __restrict__ WQ, const float* __restrict__ bQ,
                  const float* __restrict__ WK, const float* __restrict__ bK,
                  const float* __restrict__ WV, const float* __restrict__ bV,
                  int n, float* __restrict__ out_h) {
    const float* W;
    const float* bias;
    __half* out;
    if (blockIdx.y == 0)      { W = WQ; bias = bQ; out = g_Q; }
    else if (blockIdx.y == 1) { W = WK; bias = bK; out = g_K; }
    else                      { W = WV; bias = bV; out = g_V; }

    __shared__ uint32_t As[128][SPAD];
    __shared__ uint32_t Bs[128][SPAD];

    const int tid  = threadIdx.x;
    const int wid  = tid >> 5;
    const int lane = tid & 31;
    const int g    = lane >> 2;
    const int t    = lane & 3;
    const int row0 = blockIdx.x * 128;
    const int mrow = wid * 16;

    // --- fused init: Q-branch zeroes out_h rows [row0, row0+128) and segsum
    if (blockIdx.y == 0) {
        float4 z = make_float4(0.f, 0.f, 0.f, 0.f);
        // out_h: 128 rows x 128 floats = 4096 float4; 16 per thread
#pragma unroll
        for (int i = 0; i < 16; i++) {
            int idx = tid + i * 256;          // float4 index in tile
            int r   = row0 + (idx >> 5);
            if (r < n)
                *(float4*)(out_h + (size_t)r * DIMH + (idx & 31) * 4) = z;
        }
        // segsum: 128 rows x 8 floats = 256 float4; 1 per thread
        {
            int r = row0 + (tid >> 1);
            if (r < n)
                *(float4*)(g_segsum + (size_t)r * NHEADS + (tid & 1) * 4) = z;
        }
    }

    float acc[16][4];
#pragma unroll
    for (int nt = 0; nt < 16; nt++)
#pragma unroll
        for (int j = 0; j < 4; j++) acc[nt][j] = 0.0f;

    for (int kc = 0; kc < DIMH; kc += BK) {
#pragma unroll
        for (int i = 0; i < 4; i++) {
            int idx = tid + i * 256;
            int row = idx >> 3;
            int c4  = idx & 7;
            int gr  = row0 + row;
            float4 a = make_float4(0.f, 0.f, 0.f, 0.f);
            if (gr < n) a = *(const float4*)(x + (size_t)gr * DIMH + kc + c4 * 4);
            As[row][c4 * 4 + 0] = f32_to_tf32(a.x);
            As[row][c4 * 4 + 1] = f32_to_tf32(a.y);
            As[row][c4 * 4 + 2] = f32_to_tf32(a.z);
            As[row][c4 * 4 + 3] = f32_to_tf32(a.w);

            float4 w = *(const float4*)(W + (size_t)row * DIMH + kc + c4 * 4);
            Bs[row][c4 * 4 + 0] = f32_to_tf32(w.x);
            Bs[row][c4 * 4 + 1] = f32_to_tf32(w.y);
            Bs[row][c4 * 4 + 2] = f32_to_tf32(w.z);
            Bs[row][c4 * 4 + 3] = f32_to_tf32(w.w);
        }
        __syncthreads();

#pragma unroll
        for (int ks = 0; ks < BK / 8; ks++) {
            int k0 = ks * 8;
            uint32_t a0 = As[mrow + g][k0 + t];
            uint32_t a1 = As[mrow + g + 8][k0 + t];
            uint32_t a2 = As[mrow + g][k0 + t + 4];
            uint32_t a3 = As[mrow + g + 8][k0 + t + 4];
#pragma unroll
            for (int nt = 0; nt < 16; nt++) {
                uint32_t b0 = Bs[nt * 8 + g][k0 + t];
                uint32_t b1 = Bs[nt * 8 + g][k0 + t + 4];
                mma_tf32(acc[nt], a0, a1, a2, a3, b0, b1);
            }
        }
        __syncthreads();
    }

    // Epilogue: add bias, convert to fp16, store half2
    int r0 = row0 + mrow + g;
    int r1 = r0 + 8;
#pragma unroll
    for (int nt = 0; nt < 16; nt++) {
        int c = nt * 8 + 2 * t;
        float bx = __ldg(bias + c), by = __ldg(bias + c + 1);
        if (r0 < n) {
            __half2 v0 = __floats2half2_rn(acc[nt][0] + bx, acc[nt][1] + by);
            *(__half2*)(out + (size_t)r0 * DIMH + c) = v0;
        }
        if (r1 < n) {
            __half2 v1 = __floats2half2_rn(acc[nt][2] + bx, acc[nt][3] + by);
            *(__half2*)(out + (size_t)r1 * DIMH + c) = v1;
        }
    }
}

// ---------------------------------------------------------------------------
// Kernel 2 (FUSED): warp per edge.  fp16 Q/K/V loads, fp32 math, REDG out.
// ---------------------------------------------------------------------------
__global__ __launch_bounds__(256)
void fused_edge(const int* __restrict__ ei,
                const float* __restrict__ ebias,
                int E_, float* __restrict__ out_h) {
    int e    = (blockIdx.x * blockDim.x + threadIdx.x) >> 5;
    int lane = threadIdx.x & 31;
    if (e >= E_) return;

    int src = __ldg(ei + e);
    int dst = __ldg(ei + E_ + e);

    __half2 q2[2], k2[2];
    *(uint2*)q2 = *(const uint2*)(g_Q + (size_t)dst * DIMH + lane * 4);
    *(uint2*)k2 = *(const uint2*)(g_K + (size_t)src * DIMH + lane * 4);

    float2 qa = __half22float2(q2[0]), qb = __half22float2(q2[1]);
    float2 ka = __half22float2(k2[0]), kb = __half22float2(k2[1]);

    float p = qa.x * ka.x + qa.y * ka.y + qb.x * kb.x + qb.y * kb.y;
    p += __shfl_xor_sync(0xffffffffu, p, 1);
    p += __shfl_xor_sync(0xffffffffu, p, 2);

    int h = lane >> 2;
    float bias = __ldg(ebias + (size_t)e * NHEADS + h);
    float ex = __expf(p * 0.25f + bias);

    if ((lane & 3) == 0) {
        g_ex[(size_t)e * NHEADS + h] = ex;
        red_add_f32(g_segsum + (size_t)dst * NHEADS + h, ex);
    }

    __half2 v2[2];
    *(uint2*)v2 = *(const uint2*)(g_V + (size_t)src * DIMH + lane * 4);
    float2 va = __half22float2(v2[0]), vb = __half22float2(v2[1]);

    float4 v = make_float4(va.x * ex, va.y * ex, vb.x * ex, vb.y * ex);
    red_add_v4(out_h + (size_t)dst * DIMH + lane * 4, v);
}

// ---------------------------------------------------------------------------
// Kernel 3 (merged finalize):
//   t in [0, n*32): normalize out_h (thread per node-float4)
//   t in [0, e):    alpha = ex / segsum[dst] (thread per edge)
// ---------------------------------------------------------------------------
__global__ void finalize(const int* __restrict__ ei, int E_, int n,
                         float* __restrict__ out_h,
                         float* __restrict__ out_alpha) {
    int t = blockIdx.x * blockDim.x + threadIdx.x;

    if (t < n * 32) {
        int i = t >> 5;
        int c4 = t & 31;
        float s = g_segsum[(size_t)i * NHEADS + (c4 >> 2)];
        float inv = 1.0f / s;
        float4 v = *(float4*)(out_h + (size_t)i * DIMH + c4 * 4);
        v.x *= inv; v.y *= inv; v.z *= inv; v.w *= inv;
        *(float4*)(out_h + (size_t)i * DIMH + c4 * 4) = v;
    }

    if (t < E_) {
        int dst = __ldg(ei + E_ + t);
        float4 e0 = *(const float4*)(g_ex + (size_t)t * NHEADS);
        float4 e1 = *(const float4*)(g_ex + (size_t)t * NHEADS + 4);
        float4 s0 = *(const float4*)(g_segsum + (size_t)dst * NHEADS);
        float4 s1 = *(const float4*)(g_segsum + (size_t)dst * NHEADS + 4);

        e0.x /= s0.x; e0.y /= s0.y; e0.z /= s0.z; e0.w /= s0.w;
        e1.x /= s1.x; e1.y /= s1.y; e1.z /= s1.z; e1.w /= s1.w;

        *(float4*)(out_alpha + (size_t)t * NHEADS)     = e0;
        *(float4*)(out_alpha + (size_t)t * NHEADS + 4) = e1;
    }
}

// ---------------------------------------------------------------------------
// Launch
// ---------------------------------------------------------------------------
extern "C" void kernel_launch(void* const* d_in, const int* in_sizes, int n_in,
                              void* d_out, int out_size) {
    const float* x     = (const float*)d_in[0];
    const int*   ei    = (const int*)d_in[1];
    const float* ebias = (const float*)d_in[2];
    const float* WQ    = (const float*)d_in[3];
    const float* bQ    = (const float*)d_in[4];
    const float* WK    = (const float*)d_in[5];
    const float* bK    = (const float*)d_in[6];
    const float* WV    = (const float*)d_in[7];
    const float* bV    = (const float*)d_in[8];

    int n = in_sizes[0] / DIMH;     // 50000
    int e = in_sizes[1] / 2;        // 800000

    float* out_h = (float*)d_out;
    float* out_alpha = out_h + (size_t)n * DIMH;

    // 1) QKV projections (tf32 mma.sync, fp16 output) + fused zero-init
    {
        dim3 grid((n + 127) / 128, 3);
        gemm_qkv_mma<<<grid, 256>>>(x, WQ, bQ, WK, bK, WV, bV, n, out_h);
    }
    // 2) fused edge pass
    {
        long long threads = (long long)e * 32;
        int blocks = (int)((threads + 255) / 256);
        fused_edge<<<blocks, 256>>>(ei, ebias, e, out_h);
    }
    // 3) finalize: normalize h + write alpha
    {
        int total = n * 32 > e ? n * 32 : e;
        int blocks = (total + 255) / 256;
        finalize<<<blocks, 256>>>(ei, e, n, out_h, out_alpha);
    }
}